// round 2
// baseline (speedup 1.0000x reference)
#include <cuda_runtime.h>
#include <math.h>

// Problem constants (fixed by the reference: B=65536, IN=256, G=512, WIDTH=512)
#define B_ROWS 65536
#define IN_DIM 256
#define G_DIM  512
#define W_DIM  512
#define LN_EPS 1e-5f

// Scratch (device globals — no allocation allowed in kernel_launch)
__device__ float g_scaled[(size_t)B_ROWS * G_DIM];    // 128 MB: RBF activations
__device__ float g_expanded[(size_t)B_ROWS * W_DIM];  // 128 MB: pre-LN linear output
__device__ float g_xsq[B_ROWS];
__device__ float g_csq[G_DIM];
__device__ float g_s[G_DIM];

// ---------------------------------------------------------------------------
// x_sq[b] = sum_i inputs[b,i]^2   (one warp per row)
// ---------------------------------------------------------------------------
__global__ __launch_bounds__(256) void xsq_kernel(const float* __restrict__ x) {
    int warp = (blockIdx.x * blockDim.x + threadIdx.x) >> 5;
    int lane = threadIdx.x & 31;
    if (warp >= B_ROWS) return;
    const float* row = x + (size_t)warp * IN_DIM;
    float acc = 0.f;
#pragma unroll
    for (int i = 0; i < IN_DIM / 32; i++) {
        float v = row[lane + 32 * i];
        acc = fmaf(v, v, acc);
    }
#pragma unroll
    for (int o = 16; o > 0; o >>= 1) acc += __shfl_xor_sync(0xffffffffu, acc, o);
    if (lane == 0) g_xsq[warp] = acc;
}

// ---------------------------------------------------------------------------
// c_sq[g] = sum_i centers[g,i]^2 ; s[g] = exp(log_scales[g])  (warp per center)
// ---------------------------------------------------------------------------
__global__ __launch_bounds__(256) void csq_kernel(const float* __restrict__ c,
                                                  const float* __restrict__ ls) {
    int warp = (blockIdx.x * blockDim.x + threadIdx.x) >> 5;
    int lane = threadIdx.x & 31;
    if (warp >= G_DIM) return;
    const float* row = c + (size_t)warp * IN_DIM;
    float acc = 0.f;
#pragma unroll
    for (int i = 0; i < IN_DIM / 32; i++) {
        float v = row[lane + 32 * i];
        acc = fmaf(v, v, acc);
    }
#pragma unroll
    for (int o = 16; o > 0; o >>= 1) acc += __shfl_xor_sync(0xffffffffu, acc, o);
    if (lane == 0) {
        g_csq[warp] = acc;
        g_s[warp] = expf(ls[warp]);
    }
}

// ---------------------------------------------------------------------------
// GEMM1 + RBF epilogue:
//   cross[m,g] = sum_k inputs[m,k] * centers[g,k]        (NT, K=256)
//   g_scaled[m,g] = exp(-(xsq[m] + csq[g] - 2*cross) * s[g])
// 128x128 CTA tile, BK=8, 256 threads, 8x8 per-thread microtile.
// ---------------------------------------------------------------------------
__global__ __launch_bounds__(256) void gemm1_kernel(const float* __restrict__ A,
                                                    const float* __restrict__ Cn) {
    __shared__ float As[8][128];
    __shared__ float Bs[8][128];
    const int m0 = blockIdx.y * 128;
    const int n0 = blockIdx.x * 128;
    const int tid = threadIdx.x;
    const int lr = tid >> 1;          // load row 0..127
    const int lc = (tid & 1) * 4;     // load col 0 or 4
    const int tx = tid & 15;          // microtile col group
    const int ty = tid >> 4;          // microtile row group

    float acc[8][8] = {};

    for (int k0 = 0; k0 < IN_DIM; k0 += 8) {
        float4 av = *(const float4*)(A  + (size_t)(m0 + lr) * IN_DIM + k0 + lc);
        float4 bv = *(const float4*)(Cn + (size_t)(n0 + lr) * IN_DIM + k0 + lc);
        As[lc + 0][lr] = av.x; As[lc + 1][lr] = av.y;
        As[lc + 2][lr] = av.z; As[lc + 3][lr] = av.w;
        Bs[lc + 0][lr] = bv.x; Bs[lc + 1][lr] = bv.y;
        Bs[lc + 2][lr] = bv.z; Bs[lc + 3][lr] = bv.w;
        __syncthreads();
#pragma unroll
        for (int k = 0; k < 8; k++) {
            float ra[8], rb[8];
#pragma unroll
            for (int i = 0; i < 8; i++) ra[i] = As[k][ty * 8 + i];
#pragma unroll
            for (int j = 0; j < 8; j++) rb[j] = Bs[k][tx * 8 + j];
#pragma unroll
            for (int i = 0; i < 8; i++)
#pragma unroll
                for (int j = 0; j < 8; j++)
                    acc[i][j] = fmaf(ra[i], rb[j], acc[i][j]);
        }
        __syncthreads();
    }

#pragma unroll
    for (int i = 0; i < 8; i++) {
        const int m = m0 + ty * 8 + i;
        const float xq = g_xsq[m];
#pragma unroll
        for (int j = 0; j < 8; j++) {
            const int g = n0 + tx * 8 + j;
            const float d2 = xq + g_csq[g] - 2.0f * acc[i][j];
            g_scaled[(size_t)m * G_DIM + g] = expf(-d2 * g_s[g]);
        }
    }
}

// ---------------------------------------------------------------------------
// GEMM2 + bias:
//   g_expanded[m,w] = sum_g g_scaled[m,g] * W[w,g] + b[w]   (NT, K=512)
// ---------------------------------------------------------------------------
__global__ __launch_bounds__(256) void gemm2_kernel(const float* __restrict__ W,
                                                    const float* __restrict__ b) {
    __shared__ float As[8][128];
    __shared__ float Bs[8][128];
    const int m0 = blockIdx.y * 128;
    const int n0 = blockIdx.x * 128;
    const int tid = threadIdx.x;
    const int lr = tid >> 1;
    const int lc = (tid & 1) * 4;
    const int tx = tid & 15;
    const int ty = tid >> 4;

    float acc[8][8] = {};

    for (int k0 = 0; k0 < G_DIM; k0 += 8) {
        float4 av = *(const float4*)(g_scaled + (size_t)(m0 + lr) * G_DIM + k0 + lc);
        float4 bv = *(const float4*)(W        + (size_t)(n0 + lr) * G_DIM + k0 + lc);
        As[lc + 0][lr] = av.x; As[lc + 1][lr] = av.y;
        As[lc + 2][lr] = av.z; As[lc + 3][lr] = av.w;
        Bs[lc + 0][lr] = bv.x; Bs[lc + 1][lr] = bv.y;
        Bs[lc + 2][lr] = bv.z; Bs[lc + 3][lr] = bv.w;
        __syncthreads();
#pragma unroll
        for (int k = 0; k < 8; k++) {
            float ra[8], rb[8];
#pragma unroll
            for (int i = 0; i < 8; i++) ra[i] = As[k][ty * 8 + i];
#pragma unroll
            for (int j = 0; j < 8; j++) rb[j] = Bs[k][tx * 8 + j];
#pragma unroll
            for (int i = 0; i < 8; i++)
#pragma unroll
                for (int j = 0; j < 8; j++)
                    acc[i][j] = fmaf(ra[i], rb[j], acc[i][j]);
        }
        __syncthreads();
    }

#pragma unroll
    for (int i = 0; i < 8; i++) {
        const int m = m0 + ty * 8 + i;
#pragma unroll
        for (int j = 0; j < 8; j++) {
            const int w = n0 + tx * 8 + j;
            g_expanded[(size_t)m * W_DIM + w] = acc[i][j] + b[w];
        }
    }
}

// ---------------------------------------------------------------------------
// LayerNorm(512) + tanh, one block (256 threads) per row.
// ---------------------------------------------------------------------------
__global__ __launch_bounds__(256) void ln_tanh_kernel(const float* __restrict__ gamma,
                                                      const float* __restrict__ beta,
                                                      float* __restrict__ out) {
    const int row = blockIdx.x;
    const float* e = g_expanded + (size_t)row * W_DIM;
    const int tid = threadIdx.x;

    float v0 = e[tid];
    float v1 = e[tid + 256];
    float s = v0 + v1;
    float sq = v0 * v0 + v1 * v1;
#pragma unroll
    for (int o = 16; o > 0; o >>= 1) {
        s  += __shfl_xor_sync(0xffffffffu, s,  o);
        sq += __shfl_xor_sync(0xffffffffu, sq, o);
    }
    __shared__ float ss[8], ssq[8];
    const int w = tid >> 5, l = tid & 31;
    if (l == 0) { ss[w] = s; ssq[w] = sq; }
    __syncthreads();
    if (w == 0) {
        s  = (l < 8) ? ss[l]  : 0.f;
        sq = (l < 8) ? ssq[l] : 0.f;
#pragma unroll
        for (int o = 4; o > 0; o >>= 1) {
            s  += __shfl_xor_sync(0xffffffffu, s,  o);
            sq += __shfl_xor_sync(0xffffffffu, sq, o);
        }
        if (l == 0) { ss[0] = s; ssq[0] = sq; }
    }
    __syncthreads();
    const float mean = ss[0] * (1.0f / W_DIM);
    const float var  = ssq[0] * (1.0f / W_DIM) - mean * mean;
    const float rstd = rsqrtf(var + LN_EPS);

    out[(size_t)row * W_DIM + tid]       = tanhf((v0 - mean) * rstd * gamma[tid]       + beta[tid]);
    out[(size_t)row * W_DIM + tid + 256] = tanhf((v1 - mean) * rstd * gamma[tid + 256] + beta[tid + 256]);
}

// ---------------------------------------------------------------------------
extern "C" void kernel_launch(void* const* d_in, const int* in_sizes, int n_in,
                              void* d_out, int out_size) {
    const float* inputs     = (const float*)d_in[0];  // (B, IN)
    const float* centers    = (const float*)d_in[1];  // (G, IN)
    const float* log_scales = (const float*)d_in[2];  // (G,)
    const float* W_mix      = (const float*)d_in[3];  // (WIDTH, G)
    const float* b_mix      = (const float*)d_in[4];  // (WIDTH,)
    const float* ln_gamma   = (const float*)d_in[5];  // (WIDTH,)
    const float* ln_beta    = (const float*)d_in[6];  // (WIDTH,)
    float* out = (float*)d_out;                       // (B, WIDTH)

    xsq_kernel<<<B_ROWS / 8, 256>>>(inputs);
    csq_kernel<<<G_DIM / 8, 256>>>(centers, log_scales);
    gemm1_kernel<<<dim3(G_DIM / 128, B_ROWS / 128), 256>>>(inputs, centers);
    gemm2_kernel<<<dim3(W_DIM / 128, B_ROWS / 128), 256>>>(W_mix, b_mix);
    ln_tanh_kernel<<<B_ROWS, 256>>>(ln_gamma, ln_beta, out);
}

// round 4
// speedup vs baseline: 4.5929x; 4.5929x over previous
#include <cuda_runtime.h>
#include <cuda_bf16.h>
#include <math.h>
#include <stdint.h>

#define B_ROWS 65536
#define IN_DIM 256
#define G_DIM  512
#define W_DIM  512
#define LN_EPS 1e-5f

// ---------------- global scratch (device globals; no allocs) ----------------
__device__ __nv_bfloat16 g_xb[(size_t)B_ROWS * IN_DIM];   // inputs bf16
__device__ __nv_bfloat16 g_cb[(size_t)G_DIM * IN_DIM];    // centers bf16
__device__ __nv_bfloat16 g_wb[(size_t)W_DIM * G_DIM];     // W_mix bf16
__device__ __nv_bfloat16 g_scaled[(size_t)B_ROWS * G_DIM];// RBF activations bf16
__device__ float g_expanded[(size_t)B_ROWS * W_DIM];      // pre-LN fp32
__device__ float g_xsq[B_ROWS];
__device__ float g_csq[G_DIM];
__device__ float g_s[G_DIM];

// ---------------- PTX helpers (portable sm_80+ subset; compute_103-safe) ----
__device__ __forceinline__ uint32_t smem_cast(const void* p) {
    return (uint32_t)__cvta_generic_to_shared(p);
}
__device__ __forceinline__ void cp16(uint32_t dst, const void* src) {
    asm volatile("cp.async.cg.shared.global [%0], [%1], 16;" :: "r"(dst), "l"(src));
}
#define CP_COMMIT() asm volatile("cp.async.commit_group;" ::: "memory")
#define CP_WAIT1()  asm volatile("cp.async.wait_group 1;" ::: "memory")
#define CP_WAIT0()  asm volatile("cp.async.wait_group 0;" ::: "memory")

__device__ __forceinline__ void ldsm4(uint32_t* r, uint32_t addr) {
    asm volatile("ldmatrix.sync.aligned.m8n8.x4.shared.b16 {%0,%1,%2,%3}, [%4];"
                 : "=r"(r[0]), "=r"(r[1]), "=r"(r[2]), "=r"(r[3]) : "r"(addr));
}
__device__ __forceinline__ void mma_bf16(float* d, const uint32_t* a,
                                         uint32_t b0, uint32_t b1) {
    asm volatile(
        "mma.sync.aligned.m16n8k16.row.col.f32.bf16.bf16.f32 "
        "{%0,%1,%2,%3}, {%4,%5,%6,%7}, {%8,%9}, {%0,%1,%2,%3};"
        : "+f"(d[0]), "+f"(d[1]), "+f"(d[2]), "+f"(d[3])
        : "r"(a[0]), "r"(a[1]), "r"(a[2]), "r"(a[3]), "r"(b0), "r"(b1));
}

// ---------------- prep kernels ----------------------------------------------
// warp per row: row-sumsq + fp32 -> bf16 convert (linear K-contiguous layout)
__global__ __launch_bounds__(256) void conv_x(const float* __restrict__ x) {
    int row = blockIdx.x * 8 + (threadIdx.x >> 5);
    int lane = threadIdx.x & 31;
    const float* r = x + (size_t)row * IN_DIM;
    int k0 = lane * 8;
    float4 a0 = *(const float4*)(r + k0);
    float4 a1 = *(const float4*)(r + k0 + 4);
    float ss = a0.x*a0.x + a0.y*a0.y + a0.z*a0.z + a0.w*a0.w +
               a1.x*a1.x + a1.y*a1.y + a1.z*a1.z + a1.w*a1.w;
#pragma unroll
    for (int o = 16; o > 0; o >>= 1) ss += __shfl_xor_sync(0xffffffffu, ss, o);
    if (lane == 0) g_xsq[row] = ss;
    __nv_bfloat162 h0 = __floats2bfloat162_rn(a0.x, a0.y);
    __nv_bfloat162 h1 = __floats2bfloat162_rn(a0.z, a0.w);
    __nv_bfloat162 h2 = __floats2bfloat162_rn(a1.x, a1.y);
    __nv_bfloat162 h3 = __floats2bfloat162_rn(a1.z, a1.w);
    *(uint4*)(g_xb + (size_t)row * IN_DIM + k0) =
        make_uint4(*(uint32_t*)&h0, *(uint32_t*)&h1, *(uint32_t*)&h2, *(uint32_t*)&h3);
}

__global__ __launch_bounds__(256) void conv_c(const float* __restrict__ c,
                                              const float* __restrict__ ls) {
    int g = blockIdx.x * 8 + (threadIdx.x >> 5);
    int lane = threadIdx.x & 31;
    const float* r = c + (size_t)g * IN_DIM;
    int k0 = lane * 8;
    float4 a0 = *(const float4*)(r + k0);
    float4 a1 = *(const float4*)(r + k0 + 4);
    float ss = a0.x*a0.x + a0.y*a0.y + a0.z*a0.z + a0.w*a0.w +
               a1.x*a1.x + a1.y*a1.y + a1.z*a1.z + a1.w*a1.w;
#pragma unroll
    for (int o = 16; o > 0; o >>= 1) ss += __shfl_xor_sync(0xffffffffu, ss, o);
    if (lane == 0) { g_csq[g] = ss; g_s[g] = expf(ls[g]); }
    __nv_bfloat162 h0 = __floats2bfloat162_rn(a0.x, a0.y);
    __nv_bfloat162 h1 = __floats2bfloat162_rn(a0.z, a0.w);
    __nv_bfloat162 h2 = __floats2bfloat162_rn(a1.x, a1.y);
    __nv_bfloat162 h3 = __floats2bfloat162_rn(a1.z, a1.w);
    *(uint4*)(g_cb + (size_t)g * IN_DIM + k0) =
        make_uint4(*(uint32_t*)&h0, *(uint32_t*)&h1, *(uint32_t*)&h2, *(uint32_t*)&h3);
}

__global__ __launch_bounds__(256) void conv_w(const float* __restrict__ w) {
    int wr = blockIdx.x * 8 + (threadIdx.x >> 5);
    int lane = threadIdx.x & 31;
    const float* r = w + (size_t)wr * G_DIM;
#pragma unroll
    for (int part = 0; part < 2; part++) {
        int k0 = lane * 16 + part * 8;
        float4 a0 = *(const float4*)(r + k0);
        float4 a1 = *(const float4*)(r + k0 + 4);
        __nv_bfloat162 h0 = __floats2bfloat162_rn(a0.x, a0.y);
        __nv_bfloat162 h1 = __floats2bfloat162_rn(a0.z, a0.w);
        __nv_bfloat162 h2 = __floats2bfloat162_rn(a1.x, a1.y);
        __nv_bfloat162 h3 = __floats2bfloat162_rn(a1.z, a1.w);
        *(uint4*)(g_wb + (size_t)wr * G_DIM + k0) =
            make_uint4(*(uint32_t*)&h0, *(uint32_t*)&h1, *(uint32_t*)&h2, *(uint32_t*)&h3);
    }
}

// ---------------- tensor-core GEMM (mma.sync bf16, 128x128 tile) -------------
// RBF=true : C = x . centers^T (K=256), epilogue exp(-(xq+cq-2acc)*s) -> g_scaled bf16
// RBF=false: C = scaled . W^T  (K=512), epilogue +bias -> g_expanded fp32
#define SPITCH 40  // bf16 elements per smem row (16B-aligned, phase-conflict-free)

template<int KTOT, bool RBF>
__global__ __launch_bounds__(256) void gemm_mma(const float* __restrict__ bias) {
    __shared__ __align__(16) __nv_bfloat16 sm[4 * 128 * SPITCH]; // As[2] then Bs[2]
    __shared__ float s_c0[128], s_c1[128];

    const int tid = threadIdx.x, lane = tid & 31, wid = tid >> 5;
    const int bm = blockIdx.y * 128, bn = blockIdx.x * 128;
    const __nv_bfloat16* gA = RBF ? g_xb : g_scaled;
    const __nv_bfloat16* gB = RBF ? g_cb : g_wb;

    if (tid < 128) {
        if (RBF) { s_c0[tid] = g_csq[bn + tid]; s_c1[tid] = g_s[bn + tid]; }
        else     { s_c0[tid] = bias[bn + tid]; }
    }

    const uint32_t sa = smem_cast(sm);                       // As base
    const uint32_t sb = sa + 2 * 128 * SPITCH * 2;           // Bs base (bytes)
    const int lrow = tid >> 2;            // 0..63
    const int lcol = (tid & 3) * 8;       // bf16 col within k32 chunk

    // per-thread gmem row pointers (advance by 32 bf16 per chunk)
    const __nv_bfloat16* pA = gA + (size_t)(bm + lrow) * KTOT + lcol;
    const __nv_bfloat16* pB = gB + (size_t)(bn + lrow) * KTOT + lcol;
    const uint32_t dA0 = sa + (uint32_t)(lrow * SPITCH + lcol) * 2;
    const uint32_t dA1 = sa + (uint32_t)((lrow + 64) * SPITCH + lcol) * 2;
    const uint32_t dB0 = sb + (uint32_t)(lrow * SPITCH + lcol) * 2;
    const uint32_t dB1 = sb + (uint32_t)((lrow + 64) * SPITCH + lcol) * 2;
    const uint32_t bufB = 128 * SPITCH * 2;                  // buffer stride bytes

    float acc[4][4][4] = {};
    const int m0 = (wid >> 2) * 64, n0 = (wid & 3) * 32;
    const int arow = lane & 15, acol = (lane >> 4) << 3;
    const int brow = (lane & 7) | ((lane & 16) >> 1), bcol = lane & 8;

    const int NK = KTOT / 32;
    // prologue: chunk 0 -> buf 0
    {
        cp16(dA0, pA);            cp16(dA1, pA + (size_t)64 * KTOT);
        cp16(dB0, pB);            cp16(dB1, pB + (size_t)64 * KTOT);
        CP_COMMIT();
    }
    int buf = 0;
#pragma unroll 1
    for (int kc = 0; kc < NK; kc++) {
        if (kc + 1 < NK) {
            const int nb = buf ^ 1;
            const __nv_bfloat16* a = pA + (kc + 1) * 32;
            const __nv_bfloat16* b = pB + (kc + 1) * 32;
            cp16(dA0 + nb * bufB, a); cp16(dA1 + nb * bufB, a + (size_t)64 * KTOT);
            cp16(dB0 + nb * bufB, b); cp16(dB1 + nb * bufB, b + (size_t)64 * KTOT);
            CP_COMMIT();
            CP_WAIT1();
        } else {
            CP_WAIT0();
        }
        __syncthreads();

        const uint32_t abase = sa + buf * bufB;
        const uint32_t bbase = sb + buf * bufB;
#pragma unroll
        for (int kk = 0; kk < 2; kk++) {
            uint32_t af[4][4];
#pragma unroll
            for (int mf = 0; mf < 4; mf++)
                ldsm4(af[mf], abase + (uint32_t)((m0 + mf * 16 + arow) * SPITCH +
                                                 kk * 16 + acol) * 2);
            uint32_t bfr[2][4];
#pragma unroll
            for (int nh = 0; nh < 2; nh++)
                ldsm4(bfr[nh], bbase + (uint32_t)((n0 + nh * 16 + brow) * SPITCH +
                                                  kk * 16 + bcol) * 2);
#pragma unroll
            for (int mf = 0; mf < 4; mf++)
#pragma unroll
                for (int nf = 0; nf < 4; nf++)
                    mma_bf16(acc[mf][nf], af[mf],
                             bfr[nf >> 1][(nf & 1) * 2], bfr[nf >> 1][(nf & 1) * 2 + 1]);
        }
        __syncthreads();
        buf ^= 1;
    }

    // -------- epilogue --------
    const int erow = lane >> 2, ecol = (lane & 3) * 2;
#pragma unroll
    for (int mf = 0; mf < 4; mf++) {
        const int gm0 = bm + m0 + mf * 16 + erow;
        float xq0 = 0.f, xq1 = 0.f;
        if (RBF) { xq0 = g_xsq[gm0]; xq1 = g_xsq[gm0 + 8]; }
#pragma unroll
        for (int nf = 0; nf < 4; nf++) {
            const int cl = n0 + nf * 8 + ecol;     // local col 0..127 (even)
            const int gc = bn + cl;
            if (RBF) {
                const float cq0 = s_c0[cl], ss0 = s_c1[cl];
                const float cq1 = s_c0[cl + 1], ss1 = s_c1[cl + 1];
                float v00 = __expf((2.f * acc[mf][nf][0] - xq0 - cq0) * ss0);
                float v01 = __expf((2.f * acc[mf][nf][1] - xq0 - cq1) * ss1);
                float v10 = __expf((2.f * acc[mf][nf][2] - xq1 - cq0) * ss0);
                float v11 = __expf((2.f * acc[mf][nf][3] - xq1 - cq1) * ss1);
                __nv_bfloat162 h0 = __floats2bfloat162_rn(v00, v01);
                __nv_bfloat162 h1 = __floats2bfloat162_rn(v10, v11);
                *(uint32_t*)(g_scaled + (size_t)gm0 * G_DIM + gc) = *(uint32_t*)&h0;
                *(uint32_t*)(g_scaled + (size_t)(gm0 + 8) * G_DIM + gc) = *(uint32_t*)&h1;
            } else {
                const float b0 = s_c0[cl], b1 = s_c0[cl + 1];
                float2 r0 = make_float2(acc[mf][nf][0] + b0, acc[mf][nf][1] + b1);
                float2 r1 = make_float2(acc[mf][nf][2] + b0, acc[mf][nf][3] + b1);
                *(float2*)(g_expanded + (size_t)gm0 * W_DIM + gc) = r0;
                *(float2*)(g_expanded + (size_t)(gm0 + 8) * W_DIM + gc) = r1;
            }
        }
    }
}

// ---------------- LayerNorm(512) + tanh (proven round-1 kernel) --------------
__global__ __launch_bounds__(256) void ln_tanh_kernel(const float* __restrict__ gamma,
                                                      const float* __restrict__ beta,
                                                      float* __restrict__ out) {
    const int row = blockIdx.x;
    const float* e = g_expanded + (size_t)row * W_DIM;
    const int tid = threadIdx.x;

    float v0 = e[tid];
    float v1 = e[tid + 256];
    float s = v0 + v1;
    float sq = v0 * v0 + v1 * v1;
#pragma unroll
    for (int o = 16; o > 0; o >>= 1) {
        s  += __shfl_xor_sync(0xffffffffu, s,  o);
        sq += __shfl_xor_sync(0xffffffffu, sq, o);
    }
    __shared__ float ss[8], ssq[8];
    const int w = tid >> 5, l = tid & 31;
    if (l == 0) { ss[w] = s; ssq[w] = sq; }
    __syncthreads();
    if (w == 0) {
        s  = (l < 8) ? ss[l]  : 0.f;
        sq = (l < 8) ? ssq[l] : 0.f;
#pragma unroll
        for (int o = 4; o > 0; o >>= 1) {
            s  += __shfl_xor_sync(0xffffffffu, s,  o);
            sq += __shfl_xor_sync(0xffffffffu, sq, o);
        }
        if (l == 0) { ss[0] = s; ssq[0] = sq; }
    }
    __syncthreads();
    const float mean = ss[0] * (1.0f / W_DIM);
    const float var  = ssq[0] * (1.0f / W_DIM) - mean * mean;
    const float rstd = rsqrtf(var + LN_EPS);

    out[(size_t)row * W_DIM + tid]       = tanhf((v0 - mean) * rstd * gamma[tid]       + beta[tid]);
    out[(size_t)row * W_DIM + tid + 256] = tanhf((v1 - mean) * rstd * gamma[tid + 256] + beta[tid + 256]);
}

// ---------------------------------------------------------------------------
extern "C" void kernel_launch(void* const* d_in, const int* in_sizes, int n_in,
                              void* d_out, int out_size) {
    const float* inputs     = (const float*)d_in[0];
    const float* centers    = (const float*)d_in[1];
    const float* log_scales = (const float*)d_in[2];
    const float* W_mix      = (const float*)d_in[3];
    const float* b_mix      = (const float*)d_in[4];
    const float* ln_gamma   = (const float*)d_in[5];
    const float* ln_beta    = (const float*)d_in[6];
    float* out = (float*)d_out;

    conv_x<<<B_ROWS / 8, 256>>>(inputs);
    conv_c<<<G_DIM / 8, 256>>>(centers, log_scales);
    conv_w<<<W_DIM / 8, 256>>>(W_mix);
    gemm_mma<IN_DIM, true ><<<dim3(G_DIM / 128, B_ROWS / 128), 256>>>(nullptr);
    gemm_mma<G_DIM,  false><<<dim3(W_DIM / 128, B_ROWS / 128), 256>>>(b_mix);
    ln_tanh_kernel<<<B_ROWS, 256>>>(ln_gamma, ln_beta, out);
}

// round 5
// speedup vs baseline: 5.4219x; 1.1805x over previous
#include <cuda_runtime.h>
#include <cuda_bf16.h>
#include <math.h>
#include <stdint.h>

#define B_ROWS 65536
#define IN_DIM 256
#define G_DIM  512
#define W_DIM  512
#define LN_EPS 1e-5f

// ---------------- global scratch (device globals; no allocs) ----------------
__device__ __nv_bfloat16 g_xb[(size_t)B_ROWS * IN_DIM];    // inputs bf16
__device__ __nv_bfloat16 g_cb[(size_t)G_DIM * IN_DIM];     // centers bf16
__device__ __nv_bfloat16 g_wb[(size_t)W_DIM * G_DIM];      // W_mix bf16
__device__ __nv_bfloat16 g_scaled[(size_t)B_ROWS * G_DIM]; // RBF activations bf16
__device__ float g_xsq[B_ROWS];
__device__ float g_csq[G_DIM];
__device__ float g_s[G_DIM];

// ---------------- PTX helpers (sm_80+ subset; compute_103-safe) -------------
__device__ __forceinline__ uint32_t smem_cast(const void* p) {
    return (uint32_t)__cvta_generic_to_shared(p);
}
__device__ __forceinline__ void cp16(uint32_t dst, const void* src) {
    asm volatile("cp.async.cg.shared.global [%0], [%1], 16;" :: "r"(dst), "l"(src));
}
#define CP_COMMIT() asm volatile("cp.async.commit_group;" ::: "memory")
#define CP_WAIT(n)  asm volatile("cp.async.wait_group %0;" :: "n"(n) : "memory")

__device__ __forceinline__ void ldsm4(uint32_t* r, uint32_t addr) {
    asm volatile("ldmatrix.sync.aligned.m8n8.x4.shared.b16 {%0,%1,%2,%3}, [%4];"
                 : "=r"(r[0]), "=r"(r[1]), "=r"(r[2]), "=r"(r[3]) : "r"(addr));
}
__device__ __forceinline__ void mma_bf16(float* d, const uint32_t* a,
                                         uint32_t b0, uint32_t b1) {
    asm volatile(
        "mma.sync.aligned.m16n8k16.row.col.f32.bf16.bf16.f32 "
        "{%0,%1,%2,%3}, {%4,%5,%6,%7}, {%8,%9}, {%0,%1,%2,%3};"
        : "+f"(d[0]), "+f"(d[1]), "+f"(d[2]), "+f"(d[3])
        : "r"(a[0]), "r"(a[1]), "r"(a[2]), "r"(a[3]), "r"(b0), "r"(b1));
}

// ---------------- prep kernels ----------------------------------------------
__global__ __launch_bounds__(256) void conv_x(const float* __restrict__ x) {
    int row = blockIdx.x * 8 + (threadIdx.x >> 5);
    int lane = threadIdx.x & 31;
    const float* r = x + (size_t)row * IN_DIM;
    int k0 = lane * 8;
    float4 a0 = *(const float4*)(r + k0);
    float4 a1 = *(const float4*)(r + k0 + 4);
    float ss = a0.x*a0.x + a0.y*a0.y + a0.z*a0.z + a0.w*a0.w +
               a1.x*a1.x + a1.y*a1.y + a1.z*a1.z + a1.w*a1.w;
#pragma unroll
    for (int o = 16; o > 0; o >>= 1) ss += __shfl_xor_sync(0xffffffffu, ss, o);
    if (lane == 0) g_xsq[row] = ss;
    __nv_bfloat162 h0 = __floats2bfloat162_rn(a0.x, a0.y);
    __nv_bfloat162 h1 = __floats2bfloat162_rn(a0.z, a0.w);
    __nv_bfloat162 h2 = __floats2bfloat162_rn(a1.x, a1.y);
    __nv_bfloat162 h3 = __floats2bfloat162_rn(a1.z, a1.w);
    *(uint4*)(g_xb + (size_t)row * IN_DIM + k0) =
        make_uint4(*(uint32_t*)&h0, *(uint32_t*)&h1, *(uint32_t*)&h2, *(uint32_t*)&h3);
}

__global__ __launch_bounds__(256) void conv_c(const float* __restrict__ c,
                                              const float* __restrict__ ls) {
    int g = blockIdx.x * 8 + (threadIdx.x >> 5);
    int lane = threadIdx.x & 31;
    const float* r = c + (size_t)g * IN_DIM;
    int k0 = lane * 8;
    float4 a0 = *(const float4*)(r + k0);
    float4 a1 = *(const float4*)(r + k0 + 4);
    float ss = a0.x*a0.x + a0.y*a0.y + a0.z*a0.z + a0.w*a0.w +
               a1.x*a1.x + a1.y*a1.y + a1.z*a1.z + a1.w*a1.w;
#pragma unroll
    for (int o = 16; o > 0; o >>= 1) ss += __shfl_xor_sync(0xffffffffu, ss, o);
    if (lane == 0) { g_csq[g] = ss; g_s[g] = expf(ls[g]); }
    __nv_bfloat162 h0 = __floats2bfloat162_rn(a0.x, a0.y);
    __nv_bfloat162 h1 = __floats2bfloat162_rn(a0.z, a0.w);
    __nv_bfloat162 h2 = __floats2bfloat162_rn(a1.x, a1.y);
    __nv_bfloat162 h3 = __floats2bfloat162_rn(a1.z, a1.w);
    *(uint4*)(g_cb + (size_t)g * IN_DIM + k0) =
        make_uint4(*(uint32_t*)&h0, *(uint32_t*)&h1, *(uint32_t*)&h2, *(uint32_t*)&h3);
}

__global__ __launch_bounds__(256) void conv_w(const float* __restrict__ w) {
    int wr = blockIdx.x * 8 + (threadIdx.x >> 5);
    int lane = threadIdx.x & 31;
    const float* r = w + (size_t)wr * G_DIM;
#pragma unroll
    for (int part = 0; part < 2; part++) {
        int k0 = lane * 16 + part * 8;
        float4 a0 = *(const float4*)(r + k0);
        float4 a1 = *(const float4*)(r + k0 + 4);
        __nv_bfloat162 h0 = __floats2bfloat162_rn(a0.x, a0.y);
        __nv_bfloat162 h1 = __floats2bfloat162_rn(a0.z, a0.w);
        __nv_bfloat162 h2 = __floats2bfloat162_rn(a1.x, a1.y);
        __nv_bfloat162 h3 = __floats2bfloat162_rn(a1.z, a1.w);
        *(uint4*)(g_wb + (size_t)wr * G_DIM + k0) =
            make_uint4(*(uint32_t*)&h0, *(uint32_t*)&h1, *(uint32_t*)&h2, *(uint32_t*)&h3);
    }
}

// ---------------- GEMM1 (RBF): 128x128 tile, K=256, 4-stage pipeline ---------
#define SPITCH 40
#define G1_OP   (128 * SPITCH)           // bf16 elems per operand per stage
#define G1_STG  (2 * G1_OP)              // A+B per stage
#define G1_SMEM (4 * G1_STG * 2 + 1024)  // bytes: 4 stages + 256 floats consts

__global__ __launch_bounds__(256) void gemm1_rbf() {
    extern __shared__ __align__(16) __nv_bfloat16 sm[];
    float* s_c0 = (float*)(sm + 4 * G1_STG);
    float* s_c1 = s_c0 + 128;

    const int tid = threadIdx.x, lane = tid & 31, wid = tid >> 5;
    const int bm = blockIdx.y * 128, bn = blockIdx.x * 128;

    if (tid < 128) { s_c0[tid] = g_csq[bn + tid]; s_c1[tid] = g_s[bn + tid]; }

    const uint32_t sbase = smem_cast(sm);
    const int lrow = tid >> 2, lcol = (tid & 3) * 8;
    const __nv_bfloat16* pA = g_xb + (size_t)(bm + lrow) * IN_DIM + lcol;
    const __nv_bfloat16* pB = g_cb + (size_t)(bn + lrow) * IN_DIM + lcol;
    const uint32_t dA0 = sbase + (uint32_t)(lrow * SPITCH + lcol) * 2;
    const uint32_t dA1 = sbase + (uint32_t)((lrow + 64) * SPITCH + lcol) * 2;
    const uint32_t dB0 = dA0 + G1_OP * 2;
    const uint32_t dB1 = dA1 + G1_OP * 2;
    const uint32_t STGB = G1_STG * 2;

    const int NK = IN_DIM / 32;  // 8
#pragma unroll
    for (int p = 0; p < 3; p++) {  // prologue: chunks 0..2
        const uint32_t o = p * STGB;
        cp16(dA0 + o, pA + p * 32); cp16(dA1 + o, pA + p * 32 + (size_t)64 * IN_DIM);
        cp16(dB0 + o, pB + p * 32); cp16(dB1 + o, pB + p * 32 + (size_t)64 * IN_DIM);
        CP_COMMIT();
    }

    float acc[4][4][4] = {};
    const int m0 = (wid >> 2) * 64, n0 = (wid & 3) * 32;
    const int arow = lane & 15, acol = (lane >> 4) << 3;
    const int brow = (lane & 7) | ((lane & 16) >> 1), bcol = lane & 8;

#pragma unroll 1
    for (int kc = 0; kc < NK; kc++) {
        CP_WAIT(2);
        __syncthreads();
        if (kc + 3 < NK) {
            const uint32_t o = ((kc + 3) & 3) * STGB;
            const int k = (kc + 3) * 32;
            cp16(dA0 + o, pA + k); cp16(dA1 + o, pA + k + (size_t)64 * IN_DIM);
            cp16(dB0 + o, pB + k); cp16(dB1 + o, pB + k + (size_t)64 * IN_DIM);
        }
        CP_COMMIT();

        const uint32_t abase = sbase + (kc & 3) * STGB;
        const uint32_t bbase = abase + G1_OP * 2;
#pragma unroll
        for (int kk = 0; kk < 2; kk++) {
            uint32_t af[4][4];
#pragma unroll
            for (int mf = 0; mf < 4; mf++)
                ldsm4(af[mf], abase + (uint32_t)((m0 + mf * 16 + arow) * SPITCH +
                                                 kk * 16 + acol) * 2);
            uint32_t bfr[2][4];
#pragma unroll
            for (int nh = 0; nh < 2; nh++)
                ldsm4(bfr[nh], bbase + (uint32_t)((n0 + nh * 16 + brow) * SPITCH +
                                                  kk * 16 + bcol) * 2);
#pragma unroll
            for (int mf = 0; mf < 4; mf++)
#pragma unroll
                for (int nf = 0; nf < 4; nf++)
                    mma_bf16(acc[mf][nf], af[mf],
                             bfr[nf >> 1][(nf & 1) * 2], bfr[nf >> 1][(nf & 1) * 2 + 1]);
        }
    }

    // epilogue: exp(-(xq+cq-2acc)*s) -> g_scaled bf16
    const int erow = lane >> 2, ecol = (lane & 3) * 2;
#pragma unroll
    for (int mf = 0; mf < 4; mf++) {
        const int gm0 = bm + m0 + mf * 16 + erow;
        const float xq0 = g_xsq[gm0], xq1 = g_xsq[gm0 + 8];
#pragma unroll
        for (int nf = 0; nf < 4; nf++) {
            const int cl = n0 + nf * 8 + ecol;
            const int gc = bn + cl;
            const float cq0 = s_c0[cl], ss0 = s_c1[cl];
            const float cq1 = s_c0[cl + 1], ss1 = s_c1[cl + 1];
            float v00 = __expf((2.f * acc[mf][nf][0] - xq0 - cq0) * ss0);
            float v01 = __expf((2.f * acc[mf][nf][1] - xq0 - cq1) * ss1);
            float v10 = __expf((2.f * acc[mf][nf][2] - xq1 - cq0) * ss0);
            float v11 = __expf((2.f * acc[mf][nf][3] - xq1 - cq1) * ss1);
            __nv_bfloat162 h0 = __floats2bfloat162_rn(v00, v01);
            __nv_bfloat162 h1 = __floats2bfloat162_rn(v10, v11);
            *(uint32_t*)(g_scaled + (size_t)gm0 * G_DIM + gc) = *(uint32_t*)&h0;
            *(uint32_t*)(g_scaled + (size_t)(gm0 + 8) * G_DIM + gc) = *(uint32_t*)&h1;
        }
    }
}

// ---------------- GEMM2 fused with LayerNorm + tanh --------------------------
// CTA: 64 rows x N=512 (full width in registers), K=512.
// A (g_scaled tile) fully resident in SMEM; B (W) 3-stage 32-wide K chunks.
#define PA 520                       // A smem pitch (bf16)
#define G2_A   (64 * PA)             // 33280 elems
#define G2_B   (512 * SPITCH)        // per stage: 20480 elems
#define G2_FLT ((size_t)(G2_A + 3 * G2_B) * 2)          // byte offset of floats
#define G2_SMEM (G2_FLT + (512 * 5 + 128) * 4)

__global__ __launch_bounds__(256) void gemm2_ln(const float* __restrict__ bias,
                                                const float* __restrict__ gamma,
                                                const float* __restrict__ beta,
                                                float* __restrict__ out) {
    extern __shared__ __align__(16) __nv_bfloat16 sm[];
    float* vs_b  = (float*)((char*)sm + G2_FLT);
    float* vs_g  = vs_b + 512;
    float* vs_be = vs_g + 512;
    float* part_sum = vs_be + 512;   // [64 rows][8 warps]
    float* part_sq  = part_sum + 512;
    float* stats    = part_sq + 512; // [64][2] mean,rstd

    const int tid = threadIdx.x, lane = tid & 31, wid = tid >> 5;
    const int bm = blockIdx.x * 64;

    for (int i = tid; i < 512; i += 256) {
        vs_b[i] = bias[i]; vs_g[i] = gamma[i]; vs_be[i] = beta[i];
    }

    const uint32_t sa = smem_cast(sm);
    const uint32_t sb = sa + G2_A * 2;

    // A: load 64x512 bf16 tile (group 0)
#pragma unroll
    for (int i = 0; i < 16; i++) {
        const int idx = tid + i * 256;
        const int row = idx >> 6, seg = idx & 63;
        cp16(sa + (uint32_t)(row * PA + seg * 8) * 2,
             g_scaled + (size_t)(bm + row) * G_DIM + seg * 8);
    }
    CP_COMMIT();
    // B prologue: chunks 0,1
#pragma unroll
    for (int p = 0; p < 2; p++) {
#pragma unroll
        for (int i = 0; i < 8; i++) {
            const int idx = tid + i * 256;
            const int row = idx >> 2, seg = idx & 3;
            cp16(sb + (uint32_t)(p * G2_B + row * SPITCH + seg * 8) * 2,
                 g_wb + (size_t)row * G_DIM + p * 32 + seg * 8);
        }
        CP_COMMIT();
    }

    float acc[4][8][4] = {};
    const int nw = wid * 64;
    const int arow = lane & 15, acol = (lane >> 4) << 3;
    const int brow = (lane & 7) | ((lane & 16) >> 1), bcol = lane & 8;

#pragma unroll 1
    for (int kc = 0; kc < 16; kc++) {
        CP_WAIT(1);
        __syncthreads();
        if (kc + 2 < 16) {
            const int st = (kc + 2) % 3;
#pragma unroll
            for (int i = 0; i < 8; i++) {
                const int idx = tid + i * 256;
                const int row = idx >> 2, seg = idx & 3;
                cp16(sb + (uint32_t)(st * G2_B + row * SPITCH + seg * 8) * 2,
                     g_wb + (size_t)row * G_DIM + (kc + 2) * 32 + seg * 8);
            }
        }
        CP_COMMIT();

        const uint32_t bbase = sb + (uint32_t)((kc % 3) * G2_B) * 2;
#pragma unroll
        for (int kk = 0; kk < 2; kk++) {
            uint32_t af[4][4];
#pragma unroll
            for (int mf = 0; mf < 4; mf++)
                ldsm4(af[mf], sa + (uint32_t)((mf * 16 + arow) * PA +
                                              kc * 32 + kk * 16 + acol) * 2);
            uint32_t bfr[4][4];
#pragma unroll
            for (int nh = 0; nh < 4; nh++)
                ldsm4(bfr[nh], bbase + (uint32_t)((nw + nh * 16 + brow) * SPITCH +
                                                  kk * 16 + bcol) * 2);
#pragma unroll
            for (int mf = 0; mf < 4; mf++)
#pragma unroll
                for (int nf = 0; nf < 8; nf++)
                    mma_bf16(acc[mf][nf], af[mf],
                             bfr[nf >> 1][(nf & 1) * 2], bfr[nf >> 1][(nf & 1) * 2 + 1]);
        }
    }

    // ----- LayerNorm + tanh epilogue (all fp32) -----
    const int ecol = (lane & 3) * 2;
#pragma unroll
    for (int mf = 0; mf < 4; mf++) {
        float s0 = 0.f, q0 = 0.f, s1 = 0.f, q1 = 0.f;
#pragma unroll
        for (int nf = 0; nf < 8; nf++) {
            const int c = nw + nf * 8 + ecol;
            float v00 = acc[mf][nf][0] + vs_b[c];
            float v01 = acc[mf][nf][1] + vs_b[c + 1];
            float v10 = acc[mf][nf][2] + vs_b[c];
            float v11 = acc[mf][nf][3] + vs_b[c + 1];
            acc[mf][nf][0] = v00; acc[mf][nf][1] = v01;
            acc[mf][nf][2] = v10; acc[mf][nf][3] = v11;
            s0 += v00 + v01; q0 += v00 * v00 + v01 * v01;
            s1 += v10 + v11; q1 += v10 * v10 + v11 * v11;
        }
#pragma unroll
        for (int o = 1; o <= 2; o <<= 1) {
            s0 += __shfl_xor_sync(0xffffffffu, s0, o);
            q0 += __shfl_xor_sync(0xffffffffu, q0, o);
            s1 += __shfl_xor_sync(0xffffffffu, s1, o);
            q1 += __shfl_xor_sync(0xffffffffu, q1, o);
        }
        if ((lane & 3) == 0) {
            const int r0 = mf * 16 + (lane >> 2);
            part_sum[r0 * 8 + wid] = s0;       part_sq[r0 * 8 + wid] = q0;
            part_sum[(r0 + 8) * 8 + wid] = s1; part_sq[(r0 + 8) * 8 + wid] = q1;
        }
    }
    __syncthreads();
    if (tid < 64) {
        float s = 0.f, q = 0.f;
#pragma unroll
        for (int w = 0; w < 8; w++) { s += part_sum[tid * 8 + w]; q += part_sq[tid * 8 + w]; }
        const float mean = s * (1.0f / 512.0f);
        const float var  = q * (1.0f / 512.0f) - mean * mean;
        stats[tid * 2] = mean;
        stats[tid * 2 + 1] = rsqrtf(var + LN_EPS);
    }
    __syncthreads();

#pragma unroll
    for (int mf = 0; mf < 4; mf++) {
        const int r0 = mf * 16 + (lane >> 2), r1 = r0 + 8;
        const float m0 = stats[r0 * 2], rs0 = stats[r0 * 2 + 1];
        const float m1 = stats[r1 * 2], rs1 = stats[r1 * 2 + 1];
#pragma unroll
        for (int nf = 0; nf < 8; nf++) {
            const int c = nw + nf * 8 + ecol;
            const float g0 = vs_g[c], g1 = vs_g[c + 1];
            const float be0 = vs_be[c], be1 = vs_be[c + 1];
            float2 y0 = make_float2(tanhf((acc[mf][nf][0] - m0) * rs0 * g0 + be0),
                                    tanhf((acc[mf][nf][1] - m0) * rs0 * g1 + be1));
            float2 y1 = make_float2(tanhf((acc[mf][nf][2] - m1) * rs1 * g0 + be0),
                                    tanhf((acc[mf][nf][3] - m1) * rs1 * g1 + be1));
            *(float2*)(out + (size_t)(bm + r0) * W_DIM + c) = y0;
            *(float2*)(out + (size_t)(bm + r1) * W_DIM + c) = y1;
        }
    }
}

// ---------------------------------------------------------------------------
extern "C" void kernel_launch(void* const* d_in, const int* in_sizes, int n_in,
                              void* d_out, int out_size) {
    const float* inputs     = (const float*)d_in[0];
    const float* centers    = (const float*)d_in[1];
    const float* log_scales = (const float*)d_in[2];
    const float* W_mix      = (const float*)d_in[3];
    const float* b_mix      = (const float*)d_in[4];
    const float* ln_gamma   = (const float*)d_in[5];
    const float* ln_beta    = (const float*)d_in[6];
    float* out = (float*)d_out;

    cudaFuncSetAttribute(gemm1_rbf, cudaFuncAttributeMaxDynamicSharedMemorySize, G1_SMEM);
    cudaFuncSetAttribute(gemm2_ln,  cudaFuncAttributeMaxDynamicSharedMemorySize, (int)G2_SMEM);

    conv_x<<<B_ROWS / 8, 256>>>(inputs);
    conv_c<<<G_DIM / 8, 256>>>(centers, log_scales);
    conv_w<<<W_DIM / 8, 256>>>(W_mix);
    gemm1_rbf<<<dim3(G_DIM / 128, B_ROWS / 128), 256, G1_SMEM>>>();
    gemm2_ln<<<B_ROWS / 64, 256, G2_SMEM>>>(b_mix, ln_gamma, ln_beta, out);
}

// round 6
// speedup vs baseline: 6.2209x; 1.1474x over previous
#include <cuda_runtime.h>
#include <cuda_bf16.h>
#include <math.h>
#include <stdint.h>

#define B_ROWS 65536
#define IN_DIM 256
#define G_DIM  512
#define W_DIM  512
#define LN_EPS 1e-5f

// ---------------- global scratch (device globals; no allocs) ----------------
__device__ __nv_bfloat16 g_xb[(size_t)B_ROWS * IN_DIM];    // inputs bf16
__device__ __nv_bfloat16 g_cb[(size_t)G_DIM * IN_DIM];     // centers bf16
__device__ __nv_bfloat16 g_wb[(size_t)W_DIM * G_DIM];      // W_mix bf16
__device__ __nv_bfloat16 g_scaled[(size_t)B_ROWS * G_DIM]; // RBF activations bf16
__device__ float g_xsq[B_ROWS];
__device__ float g_csq[G_DIM];
__device__ float g_s[G_DIM];

// ---------------- PTX helpers (sm_80+ subset; compute_103-safe) -------------
__device__ __forceinline__ uint32_t smem_cast(const void* p) {
    return (uint32_t)__cvta_generic_to_shared(p);
}
__device__ __forceinline__ void cp16(uint32_t dst, const void* src) {
    asm volatile("cp.async.cg.shared.global [%0], [%1], 16;" :: "r"(dst), "l"(src));
}
#define CP_COMMIT() asm volatile("cp.async.commit_group;" ::: "memory")
#define CP_WAIT(n)  asm volatile("cp.async.wait_group %0;" :: "n"(n) : "memory")

__device__ __forceinline__ void ldsm4(uint32_t* r, uint32_t addr) {
    asm volatile("ldmatrix.sync.aligned.m8n8.x4.shared.b16 {%0,%1,%2,%3}, [%4];"
                 : "=r"(r[0]), "=r"(r[1]), "=r"(r[2]), "=r"(r[3]) : "r"(addr));
}
__device__ __forceinline__ void mma_bf16(float* d, const uint32_t* a,
                                         uint32_t b0, uint32_t b1) {
    asm volatile(
        "mma.sync.aligned.m16n8k16.row.col.f32.bf16.bf16.f32 "
        "{%0,%1,%2,%3}, {%4,%5,%6,%7}, {%8,%9}, {%0,%1,%2,%3};"
        : "+f"(d[0]), "+f"(d[1]), "+f"(d[2]), "+f"(d[3])
        : "r"(a[0]), "r"(a[1]), "r"(a[2]), "r"(a[3]), "r"(b0), "r"(b1));
}

// ---------------- prep kernels ----------------------------------------------
__global__ __launch_bounds__(256) void conv_x(const float* __restrict__ x) {
    int row = blockIdx.x * 8 + (threadIdx.x >> 5);
    int lane = threadIdx.x & 31;
    const float* r = x + (size_t)row * IN_DIM;
    int k0 = lane * 8;
    float4 a0 = *(const float4*)(r + k0);
    float4 a1 = *(const float4*)(r + k0 + 4);
    float ss = a0.x*a0.x + a0.y*a0.y + a0.z*a0.z + a0.w*a0.w +
               a1.x*a1.x + a1.y*a1.y + a1.z*a1.z + a1.w*a1.w;
#pragma unroll
    for (int o = 16; o > 0; o >>= 1) ss += __shfl_xor_sync(0xffffffffu, ss, o);
    if (lane == 0) g_xsq[row] = ss;
    __nv_bfloat162 h0 = __floats2bfloat162_rn(a0.x, a0.y);
    __nv_bfloat162 h1 = __floats2bfloat162_rn(a0.z, a0.w);
    __nv_bfloat162 h2 = __floats2bfloat162_rn(a1.x, a1.y);
    __nv_bfloat162 h3 = __floats2bfloat162_rn(a1.z, a1.w);
    *(uint4*)(g_xb + (size_t)row * IN_DIM + k0) =
        make_uint4(*(uint32_t*)&h0, *(uint32_t*)&h1, *(uint32_t*)&h2, *(uint32_t*)&h3);
}

__global__ __launch_bounds__(256) void conv_c(const float* __restrict__ c,
                                              const float* __restrict__ ls) {
    int g = blockIdx.x * 8 + (threadIdx.x >> 5);
    int lane = threadIdx.x & 31;
    const float* r = c + (size_t)g * IN_DIM;
    int k0 = lane * 8;
    float4 a0 = *(const float4*)(r + k0);
    float4 a1 = *(const float4*)(r + k0 + 4);
    float ss = a0.x*a0.x + a0.y*a0.y + a0.z*a0.z + a0.w*a0.w +
               a1.x*a1.x + a1.y*a1.y + a1.z*a1.z + a1.w*a1.w;
#pragma unroll
    for (int o = 16; o > 0; o >>= 1) ss += __shfl_xor_sync(0xffffffffu, ss, o);
    if (lane == 0) { g_csq[g] = ss; g_s[g] = expf(ls[g]); }
    __nv_bfloat162 h0 = __floats2bfloat162_rn(a0.x, a0.y);
    __nv_bfloat162 h1 = __floats2bfloat162_rn(a0.z, a0.w);
    __nv_bfloat162 h2 = __floats2bfloat162_rn(a1.x, a1.y);
    __nv_bfloat162 h3 = __floats2bfloat162_rn(a1.z, a1.w);
    *(uint4*)(g_cb + (size_t)g * IN_DIM + k0) =
        make_uint4(*(uint32_t*)&h0, *(uint32_t*)&h1, *(uint32_t*)&h2, *(uint32_t*)&h3);
}

__global__ __launch_bounds__(256) void conv_w(const float* __restrict__ w) {
    int wr = blockIdx.x * 8 + (threadIdx.x >> 5);
    int lane = threadIdx.x & 31;
    const float* r = w + (size_t)wr * G_DIM;
#pragma unroll
    for (int part = 0; part < 2; part++) {
        int k0 = lane * 16 + part * 8;
        float4 a0 = *(const float4*)(r + k0);
        float4 a1 = *(const float4*)(r + k0 + 4);
        __nv_bfloat162 h0 = __floats2bfloat162_rn(a0.x, a0.y);
        __nv_bfloat162 h1 = __floats2bfloat162_rn(a0.z, a0.w);
        __nv_bfloat162 h2 = __floats2bfloat162_rn(a1.x, a1.y);
        __nv_bfloat162 h3 = __floats2bfloat162_rn(a1.z, a1.w);
        *(uint4*)(g_wb + (size_t)wr * G_DIM + k0) =
            make_uint4(*(uint32_t*)&h0, *(uint32_t*)&h1, *(uint32_t*)&h2, *(uint32_t*)&h3);
    }
}

// ---------------- GEMM1 (RBF): 128x128 tile, BK=64, 3 stages, frag dbuf ------
#define G1P 72
#define G1_STG ((128 + 128) * G1P)          // elems per stage (A then B)
#define G1_SMEM (3 * G1_STG * 2 + 1024)

__global__ __launch_bounds__(256, 2) void gemm1_rbf() {
    extern __shared__ __align__(16) __nv_bfloat16 sm[];
    float* s_c0 = (float*)(sm + 3 * G1_STG);
    float* s_c1 = s_c0 + 128;

    const int tid = threadIdx.x, lane = tid & 31, wid = tid >> 5;
    const int bm = blockIdx.y * 128, bn = blockIdx.x * 128;

    if (tid < 128) { s_c0[tid] = g_csq[bn + tid]; s_c1[tid] = g_s[bn + tid]; }

    const uint32_t sbase = smem_cast(sm);
    // cp.async mapping: 4 A-vec + 4 B-vec per thread per 64-K chunk
    const int crow = tid >> 3, cc8 = (tid & 7) * 8;
    const __nv_bfloat16* pA = g_xb + (size_t)(bm + crow) * IN_DIM + cc8;
    const __nv_bfloat16* pB = g_cb + (size_t)(bn + crow) * IN_DIM + cc8;
    const uint32_t dA = sbase + (uint32_t)(crow * G1P + cc8) * 2;
    const uint32_t dB = dA + (uint32_t)(128 * G1P) * 2;

    auto load_chunk = [&](int kc, int stg) {
        const uint32_t so = (uint32_t)(stg * G1_STG) * 2;
#pragma unroll
        for (int i = 0; i < 4; i++) {
            cp16(dA + so + (uint32_t)(i * 32 * G1P) * 2, pA + kc * 64 + (size_t)(i * 32) * IN_DIM);
            cp16(dB + so + (uint32_t)(i * 32 * G1P) * 2, pB + kc * 64 + (size_t)(i * 32) * IN_DIM);
        }
    };

    const int m0 = (wid >> 2) * 64, n0 = (wid & 3) * 32;
    const int arow = lane & 15, acol = (lane >> 4) << 3;
    const int brow = (lane & 7) | ((lane & 16) >> 1), bcol = lane & 8;

    float acc[4][4][4] = {};
    uint32_t af[2][4][4], bfr[2][2][4];

    auto load_frags = [&](int stg, int kk, int b) {
        const uint32_t ab = sbase + (uint32_t)(stg * G1_STG) * 2;
        const uint32_t bb = ab + (uint32_t)(128 * G1P) * 2;
#pragma unroll
        for (int mf = 0; mf < 4; mf++)
            ldsm4(af[b][mf], ab + (uint32_t)((m0 + mf * 16 + arow) * G1P + kk * 16 + acol) * 2);
#pragma unroll
        for (int nh = 0; nh < 2; nh++)
            ldsm4(bfr[b][nh], bb + (uint32_t)((n0 + nh * 16 + brow) * G1P + kk * 16 + bcol) * 2);
    };
    auto do_mma = [&](int b) {
#pragma unroll
        for (int mf = 0; mf < 4; mf++)
#pragma unroll
            for (int nf = 0; nf < 4; nf++)
                mma_bf16(acc[mf][nf], af[b][mf],
                         bfr[b][nf >> 1][(nf & 1) * 2], bfr[b][nf >> 1][(nf & 1) * 2 + 1]);
    };

    load_chunk(0, 0); CP_COMMIT();
    load_chunk(1, 1); CP_COMMIT();
    CP_WAIT(1); __syncthreads();
    load_frags(0, 0, 0);

#pragma unroll 1
    for (int kc = 0; kc < 4; kc++) {
        if (kc + 2 < 4) load_chunk(kc + 2, (kc + 2) % 3);
        CP_COMMIT();
#pragma unroll
        for (int kk = 0; kk < 4; kk++) {
            const int cur = kk & 1;
            if (kk < 3) {
                load_frags(kc % 3, kk + 1, cur ^ 1);
            } else if (kc < 3) {
                CP_WAIT(1); __syncthreads();
                load_frags((kc + 1) % 3, 0, cur ^ 1);
            }
            do_mma(cur);
        }
    }

    // epilogue: exp(-(xq+cq-2acc)*s) -> g_scaled bf16
    const int erow = lane >> 2, ecol = (lane & 3) * 2;
#pragma unroll
    for (int mf = 0; mf < 4; mf++) {
        const int gm0 = bm + m0 + mf * 16 + erow;
        const float xq0 = g_xsq[gm0], xq1 = g_xsq[gm0 + 8];
#pragma unroll
        for (int nf = 0; nf < 4; nf++) {
            const int cl = n0 + nf * 8 + ecol;
            const int gc = bn + cl;
            const float cq0 = s_c0[cl], ss0 = s_c1[cl];
            const float cq1 = s_c0[cl + 1], ss1 = s_c1[cl + 1];
            float v00 = __expf((2.f * acc[mf][nf][0] - xq0 - cq0) * ss0);
            float v01 = __expf((2.f * acc[mf][nf][1] - xq0 - cq1) * ss1);
            float v10 = __expf((2.f * acc[mf][nf][2] - xq1 - cq0) * ss0);
            float v11 = __expf((2.f * acc[mf][nf][3] - xq1 - cq1) * ss1);
            __nv_bfloat162 h0 = __floats2bfloat162_rn(v00, v01);
            __nv_bfloat162 h1 = __floats2bfloat162_rn(v10, v11);
            *(uint32_t*)(g_scaled + (size_t)gm0 * G_DIM + gc) = *(uint32_t*)&h0;
            *(uint32_t*)(g_scaled + (size_t)(gm0 + 8) * G_DIM + gc) = *(uint32_t*)&h1;
        }
    }
}

// ---------------- GEMM2 + LayerNorm + tanh: 64x512, BK=64, A resident --------
#define PA 520
#define G2P 72
#define G2_A   (64 * PA)                    // 33280 elems
#define G2_BSTG (512 * G2P)                 // 36864 elems per stage
#define G2_FLT ((size_t)(G2_A + 2 * G2_BSTG) * 2)
#define G2_SMEM (G2_FLT + (512 * 5 + 128) * 4)

__global__ __launch_bounds__(256, 1) void gemm2_ln(const float* __restrict__ bias,
                                                   const float* __restrict__ gamma,
                                                   const float* __restrict__ beta,
                                                   float* __restrict__ out) {
    extern __shared__ __align__(16) __nv_bfloat16 sm[];
    float* vs_b  = (float*)((char*)sm + G2_FLT);
    float* vs_g  = vs_b + 512;
    float* vs_be = vs_g + 512;
    float* part_sum = vs_be + 512;   // [64 rows][8 warps]
    float* part_sq  = part_sum + 512;
    float* stats    = part_sq + 512; // [64][2]

    const int tid = threadIdx.x, lane = tid & 31, wid = tid >> 5;
    const int bm = blockIdx.x * 64;

    for (int i = tid; i < 512; i += 256) {
        vs_b[i] = bias[i]; vs_g[i] = gamma[i]; vs_be[i] = beta[i];
    }

    const uint32_t sa = smem_cast(sm);
    const uint32_t sb = sa + (uint32_t)G2_A * 2;

    // A: 64x512 tile, 16 cp16/thread
    {
        const int row = tid >> 2, c8 = (tid & 3) * 8;   // base: 4 vecs/row-slice
#pragma unroll
        for (int i = 0; i < 16; i++) {
            const int idx = tid + i * 256;
            const int r = idx >> 6, c = (idx & 63) * 8;
            cp16(sa + (uint32_t)(r * PA + c) * 2,
                 g_scaled + (size_t)(bm + r) * G_DIM + c);
        }
        (void)row; (void)c8;
    }
    CP_COMMIT();

    // B chunk loader: 16 cp16/thread (512 rows x 64 cols)
    const int brw = tid >> 3, bc8 = (tid & 7) * 8;
    auto loadB = [&](int kc, int stg) {
        const uint32_t so = sb + (uint32_t)(stg * G2_BSTG) * 2;
#pragma unroll
        for (int i = 0; i < 16; i++) {
            const int r = brw + i * 32;
            cp16(so + (uint32_t)(r * G2P + bc8) * 2,
                 g_wb + (size_t)r * G_DIM + kc * 64 + bc8);
        }
    };
    loadB(0, 0); CP_COMMIT();
    loadB(1, 1); CP_COMMIT();

    const int nw = wid * 64;
    const int arow = lane & 15, acol = (lane >> 4) << 3;
    const int brow = (lane & 7) | ((lane & 16) >> 1), bcol = lane & 8;

    float acc[4][8][4] = {};
    uint32_t af[2][4][4], bfr[2][4][4];

    auto load_frags = [&](int stg, int kk, int b, int kca) {
#pragma unroll
        for (int mf = 0; mf < 4; mf++)
            ldsm4(af[b][mf], sa + (uint32_t)((mf * 16 + arow) * PA +
                                             kca * 64 + kk * 16 + acol) * 2);
        const uint32_t bb = sb + (uint32_t)(stg * G2_BSTG) * 2;
#pragma unroll
        for (int nh = 0; nh < 4; nh++)
            ldsm4(bfr[b][nh], bb + (uint32_t)((nw + nh * 16 + brow) * G2P +
                                              kk * 16 + bcol) * 2);
    };
    auto do_mma = [&](int b) {
#pragma unroll
        for (int mf = 0; mf < 4; mf++)
#pragma unroll
            for (int nf = 0; nf < 8; nf++)
                mma_bf16(acc[mf][nf], af[b][mf],
                         bfr[b][nf >> 1][(nf & 1) * 2], bfr[b][nf >> 1][(nf & 1) * 2 + 1]);
    };

    CP_WAIT(1); __syncthreads();   // A + B0 ready
    load_frags(0, 0, 0, 0);

#pragma unroll 1
    for (int kc = 0; kc < 8; kc++) {
#pragma unroll
        for (int kk = 0; kk < 4; kk++) {
            const int cur = kk & 1;
            if (kk < 3) {
                load_frags(kc & 1, kk + 1, cur ^ 1, kc);
            } else if (kc < 7) {
                CP_WAIT(0); __syncthreads();
                if (kc + 2 < 8) loadB(kc + 2, kc & 1);
                CP_COMMIT();
                load_frags((kc + 1) & 1, 0, cur ^ 1, kc + 1);
            }
            do_mma(cur);
        }
    }

    // ----- LayerNorm + tanh epilogue (fp32) -----
    const int ecol = (lane & 3) * 2;
#pragma unroll
    for (int mf = 0; mf < 4; mf++) {
        float s0 = 0.f, q0 = 0.f, s1 = 0.f, q1 = 0.f;
#pragma unroll
        for (int nf = 0; nf < 8; nf++) {
            const int c = nw + nf * 8 + ecol;
            float v00 = acc[mf][nf][0] + vs_b[c];
            float v01 = acc[mf][nf][1] + vs_b[c + 1];
            float v10 = acc[mf][nf][2] + vs_b[c];
            float v11 = acc[mf][nf][3] + vs_b[c + 1];
            acc[mf][nf][0] = v00; acc[mf][nf][1] = v01;
            acc[mf][nf][2] = v10; acc[mf][nf][3] = v11;
            s0 += v00 + v01; q0 += v00 * v00 + v01 * v01;
            s1 += v10 + v11; q1 += v10 * v10 + v11 * v11;
        }
#pragma unroll
        for (int o = 1; o <= 2; o <<= 1) {
            s0 += __shfl_xor_sync(0xffffffffu, s0, o);
            q0 += __shfl_xor_sync(0xffffffffu, q0, o);
            s1 += __shfl_xor_sync(0xffffffffu, s1, o);
            q1 += __shfl_xor_sync(0xffffffffu, q1, o);
        }
        if ((lane & 3) == 0) {
            const int r0 = mf * 16 + (lane >> 2);
            part_sum[r0 * 8 + wid] = s0;       part_sq[r0 * 8 + wid] = q0;
            part_sum[(r0 + 8) * 8 + wid] = s1; part_sq[(r0 + 8) * 8 + wid] = q1;
        }
    }
    __syncthreads();
    if (tid < 64) {
        float s = 0.f, q = 0.f;
#pragma unroll
        for (int w = 0; w < 8; w++) { s += part_sum[tid * 8 + w]; q += part_sq[tid * 8 + w]; }
        const float mean = s * (1.0f / 512.0f);
        const float var  = q * (1.0f / 512.0f) - mean * mean;
        stats[tid * 2] = mean;
        stats[tid * 2 + 1] = rsqrtf(var + LN_EPS);
    }
    __syncthreads();

#pragma unroll
    for (int mf = 0; mf < 4; mf++) {
        const int r0 = mf * 16 + (lane >> 2), r1 = r0 + 8;
        const float m0 = stats[r0 * 2], rs0 = stats[r0 * 2 + 1];
        const float m1 = stats[r1 * 2], rs1 = stats[r1 * 2 + 1];
#pragma unroll
        for (int nf = 0; nf < 8; nf++) {
            const int c = nw + nf * 8 + ecol;
            const float g0 = vs_g[c], g1 = vs_g[c + 1];
            const float be0 = vs_be[c], be1 = vs_be[c + 1];
            float2 y0 = make_float2(tanhf((acc[mf][nf][0] - m0) * rs0 * g0 + be0),
                                    tanhf((acc[mf][nf][1] - m0) * rs0 * g1 + be1));
            float2 y1 = make_float2(tanhf((acc[mf][nf][2] - m1) * rs1 * g0 + be0),
                                    tanhf((acc[mf][nf][3] - m1) * rs1 * g1 + be1));
            *(float2*)(out + (size_t)(bm + r0) * W_DIM + c) = y0;
            *(float2*)(out + (size_t)(bm + r1) * W_DIM + c) = y1;
        }
    }
}

// ---------------------------------------------------------------------------
extern "C" void kernel_launch(void* const* d_in, const int* in_sizes, int n_in,
                              void* d_out, int out_size) {
    const float* inputs     = (const float*)d_in[0];
    const float* centers    = (const float*)d_in[1];
    const float* log_scales = (const float*)d_in[2];
    const float* W_mix      = (const float*)d_in[3];
    const float* b_mix      = (const float*)d_in[4];
    const float* ln_gamma   = (const float*)d_in[5];
    const float* ln_beta    = (const float*)d_in[6];
    float* out = (float*)d_out;

    cudaFuncSetAttribute(gemm1_rbf, cudaFuncAttributeMaxDynamicSharedMemorySize, G1_SMEM);
    cudaFuncSetAttribute(gemm2_ln,  cudaFuncAttributeMaxDynamicSharedMemorySize, (int)G2_SMEM);

    conv_x<<<B_ROWS / 8, 256>>>(inputs);
    conv_c<<<G_DIM / 8, 256>>>(centers, log_scales);
    conv_w<<<W_DIM / 8, 256>>>(W_mix);
    gemm1_rbf<<<dim3(G_DIM / 128, B_ROWS / 128), 256, G1_SMEM>>>();
    gemm2_ln<<<B_ROWS / 64, 256, G2_SMEM>>>(b_mix, ln_gamma, ln_beta, out);
}